// round 14
// baseline (speedup 1.0000x reference)
#include <cuda_runtime.h>
#include <cuda_fp16.h>
#include <math.h>

#define NN 10000
#define EE 320000
#define MT_TILES 632
#define NT_TILES 1264
#define TAILB 80
#define GRID 280
#define G0 88
#define G1 192
typedef unsigned long long u64;

// ---------------- device scratch ----------------
__device__ __half g_Hh[2][NN * 128];
__device__ __half g_Xh[2][NN * 128];
__device__ float g_af[2][NN * 32];
__device__ uint4 g_fA[MT_TILES * 2 * 32];
__device__ uint2 g_fB[NT_TILES * 2 * 32];
__device__ float g_dinv[2][NN];
__device__ int   g_indeg[2][NN];
__device__ int   g_rowstart[2][NN + 1];
__device__ int   g_blocksum[2][40];
__device__ int   g_choff[2][41];
__device__ int   g_lpos[2][EE];
__device__ int2  g_adjc[2][EE];
__device__ unsigned g_keymin, g_keymax;
__device__ unsigned g_hist[16 * 32];
__device__ unsigned g_barctr[8];     // tail barriers (monotonic)
__device__ unsigned g_bar2[16];      // mega barriers (monotonic)
__device__ float g_meanraw[2][32];
__device__ float g_gc[2][32];
__device__ float g_pool[2][32];
__device__ float g_A[2][32 * 16];
__device__ float g_c[2][16];
__device__ float g_sAcc[2][16];
__device__ float g_s0[16];

// ---------------- helpers ----------------
__device__ __forceinline__ unsigned fkey(float f) {
    unsigned u = __float_as_uint(f);
    return (u & 0x80000000u) ? ~u : (u | 0x80000000u);
}
__device__ __forceinline__ float fdec(unsigned k) {
    return (k & 0x80000000u) ? __uint_as_float(k ^ 0x80000000u)
                             : __uint_as_float(~k);
}
__device__ __forceinline__ u64 dup2(float a) {
    u64 r;
    asm("mov.b64 %0, {%1, %1};" : "=l"(r) : "r"(__float_as_uint(a)));
    return r;
}
__device__ __forceinline__ void ffma2(u64& acc, u64 a, u64 b) {
    asm("fma.rn.f32x2 %0, %1, %2, %0;" : "+l"(acc) : "l"(a), "l"(b));
}
__device__ __forceinline__ void unpk(u64 v, float& lo, float& hi) {
    unsigned l, h;
    asm("mov.b64 {%0, %1}, %2;" : "=r"(l), "=r"(h) : "l"(v));
    lo = __uint_as_float(l); hi = __uint_as_float(h);
}
__device__ __forceinline__ unsigned h2pack(float a, float b) {
    __half2 h = __floats2half2_rn(a, b);
    return *(unsigned*)&h;
}
__device__ __forceinline__ void mma_f16(float c[4], uint4 a, uint2 b) {
    asm("mma.sync.aligned.m16n8k16.row.col.f32.f16.f16.f32 "
        "{%0,%1,%2,%3}, {%4,%5,%6,%7}, {%8,%9}, {%0,%1,%2,%3};"
        : "+f"(c[0]), "+f"(c[1]), "+f"(c[2]), "+f"(c[3])
        : "r"(a.x), "r"(a.y), "r"(a.z), "r"(a.w), "r"(b.x), "r"(b.y));
}
// monotonic barriers: counter never reset; target = next multiple of G
__device__ __forceinline__ void mbar(int idx, unsigned G) {
    __syncthreads();
    if (threadIdx.x == 0) {
        __threadfence();
        unsigned t = atomicAdd(&g_bar2[idx], 1u) + 1;
        unsigned target = ((t + G - 1) / G) * G;
        while (((volatile unsigned*)g_bar2)[idx] < target) { }
        __threadfence();
    }
    __syncthreads();
}
__device__ __forceinline__ void gridbar(int ph) {
    __syncthreads();
    if (threadIdx.x == 0) {
        __threadfence();
        unsigned t = atomicAdd(&g_barctr[ph], 1u) + 1;
        unsigned target = ((t + TAILB - 1) / TAILB) * TAILB;
        while (((volatile unsigned*)g_barctr)[ph] < target) { }
        __threadfence();
    }
    __syncthreads();
}

// ---------------- tgemm tile (device) ----------------
template <int FOUT, int KTOT, int RELU, int INHALF>
__device__ void tgemm_tile(const void* __restrict__ Xv, const float* __restrict__ W,
                           __half* __restrict__ H, int i0, int cb, char* smbase) {
    constexpr int COLS = (FOUT >= 64) ? 64 : FOUT;
    constexpr int CPT = COLS / 32;
    float (*As)[68] = (float (*)[68])smbase;
    float (*Ws)[COLS] = (float (*)[COLS])(smbase + 8704);
    int tid = threadIdx.x;
    int tx = tid & 31, ty = tid >> 5;
    u64 acc2[4][CPT];
#pragma unroll
    for (int r = 0; r < 4; r++)
#pragma unroll
        for (int c = 0; c < CPT; c++) acc2[r][c] = 0ull;

    for (int k0 = 0; k0 < KTOT; k0 += 32) {
        for (int idx = tid; idx < 512; idx += 256) {
            int r = idx >> 3, k4 = idx & 7;
            int row = i0 + r;
            float4 v = make_float4(0.f, 0.f, 0.f, 0.f);
            if (row < NN) {
                if (INHALF) {
                    uint2 raw = *(const uint2*)((const __half*)Xv + (size_t)row * KTOT + k0 + k4 * 4);
                    float2 a = __half22float2(*(__half2*)&raw.x);
                    float2 b = __half22float2(*(__half2*)&raw.y);
                    v = make_float4(a.x, a.y, b.x, b.y);
                } else {
                    v = *(const float4*)((const float*)Xv + (size_t)row * KTOT + k0 + k4 * 4);
                }
            }
            if (RELU) {
                v.x = fmaxf(v.x, 0.f); v.y = fmaxf(v.y, 0.f);
                v.z = fmaxf(v.z, 0.f); v.w = fmaxf(v.w, 0.f);
            }
            As[k4 * 4 + 0][r] = v.x; As[k4 * 4 + 1][r] = v.y;
            As[k4 * 4 + 2][r] = v.z; As[k4 * 4 + 3][r] = v.w;
        }
        for (int idx = tid; idx < 8 * COLS; idx += 256) {
            int j4 = idx % (COLS / 4), kk = idx / (COLS / 4);
            float4 w = *(const float4*)&W[(size_t)(k0 + kk) * FOUT + cb + j4 * 4];
            Ws[kk][j4 * 4 + 0] = w.x; Ws[kk][j4 * 4 + 1] = w.y;
            Ws[kk][j4 * 4 + 2] = w.z; Ws[kk][j4 * 4 + 3] = w.w;
        }
        __syncthreads();
#pragma unroll 4
        for (int k = 0; k < 32; k++) {
            u64 aa[4];
            {
                const ulonglong2* ap = (const ulonglong2*)&As[k][ty * 8];
                ulonglong2 t0 = ap[0], t1 = ap[1];
                aa[0] = t0.x; aa[1] = t0.y; aa[2] = t1.x; aa[3] = t1.y;
            }
            u64 bd[CPT];
            if (CPT == 2) {
                float2 b = *(const float2*)&Ws[k][tx * 2];
                bd[0] = dup2(b.x); bd[1] = dup2(b.y);
            } else {
                bd[0] = dup2(Ws[k][tx]);
            }
#pragma unroll
            for (int r = 0; r < 4; r++)
#pragma unroll
                for (int c = 0; c < CPT; c++) ffma2(acc2[r][c], aa[r], bd[c]);
        }
        __syncthreads();
    }
#pragma unroll
    for (int rp = 0; rp < 4; rp++) {
        int r0 = i0 + ty * 8 + 2 * rp;
        float lo[CPT], hi[CPT];
#pragma unroll
        for (int c = 0; c < CPT; c++) unpk(acc2[rp][c], lo[c], hi[c]);
        if (r0 < NN) {
            if (CPT == 2)
                *(__half2*)&H[(size_t)r0 * FOUT + cb + tx * 2] = __floats2half2_rn(lo[0], lo[1]);
            else
                H[(size_t)r0 * FOUT + cb + tx] = __float2half_rn(lo[0]);
        }
        if (r0 + 1 < NN) {
            if (CPT == 2)
                *(__half2*)&H[(size_t)(r0 + 1) * FOUT + cb + tx * 2] = __floats2half2_rn(hi[0], hi[1]);
            else
                H[(size_t)(r0 + 1) * FOUT + cb + tx] = __float2half_rn(hi[0]);
        }
    }
}

// ---------------- gather unit (device) ----------------
template <int OUTHALF>
__device__ __forceinline__ void gather_unit(int idx, const __half* __restrict__ H,
        const int* __restrict__ rowstart, const int2* __restrict__ adjc,
        const float* __restrict__ b, void* __restrict__ Ov, int Fout) {
    int gpf = Fout >> 2;
    int node = idx / gpf;
    int c = idx - node * gpf;
    if (node >= NN) return;
    int rs = rowstart[node], re = rowstart[node + 1];
    float invdeg = 1.0f / ((float)(re - rs) + 1.0f);
    __half2 h01, h23;
    {
        uint2 raw = *(const uint2*)(H + (size_t)node * Fout + c * 4);
        h01 = *(__half2*)&raw.x; h23 = *(__half2*)&raw.y;
    }
    float2 f01 = __half22float2(h01), f23 = __half22float2(h23);
    float4 bb = ((const float4*)b)[c];
    float4 acc;
    acc.x = f01.x * invdeg + bb.x; acc.y = f01.y * invdeg + bb.y;
    acc.z = f23.x * invdeg + bb.z; acc.w = f23.y * invdeg + bb.w;
#pragma unroll 4
    for (int e = rs; e < re; e++) {
        int2 sc = __ldg(&adjc[e]);
        float coef = __int_as_float(sc.y);
        uint2 raw = __ldg((const uint2*)(H + (size_t)sc.x * Fout) + c);
        float2 v01 = __half22float2(*(__half2*)&raw.x);
        float2 v23 = __half22float2(*(__half2*)&raw.y);
        acc.x += coef * v01.x; acc.y += coef * v01.y;
        acc.z += coef * v23.x; acc.w += coef * v23.y;
    }
    if (OUTHALF) {
        __half* O = (__half*)Ov;
        __half2 h0 = __floats2half2_rn(acc.x, acc.y);
        __half2 h1 = __floats2half2_rn(acc.z, acc.w);
        uint2 o;
        o.x = *(unsigned*)&h0; o.y = *(unsigned*)&h1;
        *(uint2*)(O + (size_t)node * Fout + c * 4) = o;
    } else {
        float* O = (float*)Ov;
        ((float4*)(O + (size_t)node * Fout))[c] = acc;
    }
}

__device__ __forceinline__ float afld(const float* af, int n, int k) {
    return (n < NN) ? af[n * 32 + k] : 0.f;
}

// ---------------- megakernel: CSR + GCN + frag ----------------
__global__ void __launch_bounds__(256, 2)
k_mega(const float* __restrict__ feat1, const float* __restrict__ feat2,
       const int* __restrict__ ei1, const int* __restrict__ ei2,
       const float* __restrict__ W1, const float* __restrict__ W2,
       const float* __restrict__ W3,
       const float* __restrict__ b1, const float* __restrict__ b2,
       const float* __restrict__ b3) {
    __shared__ __align__(16) char sm[16896];
    __shared__ int wsum[8];
    __shared__ int woff[9];
    int gid = blockIdx.x, tid = threadIdx.x;

    // ---- Phase A: split (CSR on blocks [0,G0), tgemm1 on [G0,GRID)) ----
    if (gid < G0) {
        int lid = gid;
        // reset
        for (int i = lid * 256 + tid; i < 2 * NN; i += G0 * 256)
            ((int*)g_indeg)[i] = 0;
        if (lid == 0) {
            for (int i = tid; i < 512; i += 256) g_hist[i] = 0u;
            if (tid < 32) {
                g_meanraw[0][tid] = 0.f; g_meanraw[1][tid] = 0.f;
                g_pool[0][tid] = 0.f;    g_pool[1][tid] = 0.f;
            }
            if (tid < 16) { g_sAcc[0][tid] = 0.f; g_sAcc[1][tid] = 0.f; }
            if (tid == 0) { g_keymin = 0xFFFFFFFFu; g_keymax = 0u; }
        }
        mbar(0, G0);
        // indeg (+lpos)
        for (int t = lid * 256 + tid; t < EE; t += G0 * 256) {
            int g = t >= (EE / 2);
            const int* ei = g ? ei2 : ei1;
            int e2 = (t - g * (EE / 2)) * 2;
            int2 d = *(const int2*)&ei[EE + e2];
            int p0 = atomicAdd(&g_indeg[g][d.x], 1);
            int p1 = atomicAdd(&g_indeg[g][d.y], 1);
            g_lpos[g][e2] = p0;
            g_lpos[g][e2 + 1] = p1;
        }
        mbar(1, G0);
        // chunked scan (256-node chunks; 40 per graph)
        for (int ch = lid; ch < 80; ch += G0) {
            int g = ch >= 40, c = ch - g * 40;
            int i = c * 256 + tid;
            int v = (i < NN) ? g_indeg[g][i] : 0;
            int lane = tid & 31, w = tid >> 5;
            int x = v;
#pragma unroll
            for (int o = 1; o < 32; o <<= 1) {
                int y = __shfl_up_sync(0xffffffffu, x, o);
                if (lane >= o) x += y;
            }
            if (lane == 31) wsum[w] = x;
            __syncthreads();
            if (tid == 0) {
                int r = 0;
                for (int k = 0; k < 8; k++) { woff[k] = r; r += wsum[k]; }
                woff[8] = r;
            }
            __syncthreads();
            int excl = (x - v) + woff[w];
            if (i < NN) {
                g_rowstart[g][i] = excl;
                g_dinv[g][i] = rsqrtf((float)v + 1.0f);
            }
            if (tid == 0) g_blocksum[g][c] = woff[8];
            __syncthreads();
        }
        mbar(2, G0);
        if (lid == 0 && tid < 2) {
            int run = 0;
            for (int c = 0; c < 40; c++) { g_choff[tid][c] = run; run += g_blocksum[tid][c]; }
            g_choff[tid][40] = run;
            g_rowstart[tid][NN] = run;
        }
        mbar(3, G0);
        for (int i = lid * 256 + tid; i < 2 * NN; i += G0 * 256) {
            int g = i >= NN;
            int n = i - g * NN;
            g_rowstart[g][n] += g_choff[g][n >> 8];
        }
        mbar(4, G0);
        // fill
        for (int t = lid * 256 + tid; t < EE; t += G0 * 256) {
            int g = t >= (EE / 2);
            const int* ei = g ? ei2 : ei1;
            int e2 = (t - g * (EE / 2)) * 2;
            int2 s = *(const int2*)&ei[e2];
            int2 d = *(const int2*)&ei[EE + e2];
            int lp0 = g_lpos[g][e2], lp1 = g_lpos[g][e2 + 1];
            float c0 = g_dinv[g][s.x] * g_dinv[g][d.x];
            float c1 = g_dinv[g][s.y] * g_dinv[g][d.y];
            g_adjc[g][g_rowstart[g][d.x] + lp0] = make_int2(s.x, __float_as_int(c0));
            g_adjc[g][g_rowstart[g][d.y] + lp1] = make_int2(s.y, __float_as_int(c1));
        }
    } else {
        // layer-1 GEMM tiles: 628 = 2 graphs x 2 col-halves x 157
        for (int tt = gid - G0; tt < 628; tt += G1) {
            int z = tt / 314, rem = tt - z * 314;
            int cbi = rem / 157, bx = rem - cbi * 157;
            tgemm_tile<128, 128, 0, 0>(z ? (const void*)feat2 : (const void*)feat1,
                                       W1, g_Hh[z], bx * 64, cbi * 64, sm);
        }
    }
    mbar(5, GRID);
    // gather1
    for (int u = gid; u < 2500; u += GRID) {
        int z = u / 1250, ub = u - z * 1250;
        gather_unit<1>(ub * 256 + tid, g_Hh[z], g_rowstart[z], g_adjc[z], b1, g_Xh[z], 128);
    }
    mbar(6, GRID);
    // tgemm2
    for (int tt = gid; tt < 314; tt += GRID) {
        int z = tt / 157, bx = tt - z * 157;
        tgemm_tile<64, 128, 1, 1>(g_Xh[z], W2, g_Hh[z], bx * 64, 0, sm);
    }
    mbar(7, GRID);
    // gather2
    for (int u = gid; u < 1250; u += GRID) {
        int z = u / 625, ub = u - z * 625;
        gather_unit<1>(ub * 256 + tid, g_Hh[z], g_rowstart[z], g_adjc[z], b2, g_Xh[z], 64);
    }
    mbar(8, GRID);
    // tgemm3
    for (int tt = gid; tt < 314; tt += GRID) {
        int z = tt / 157, bx = tt - z * 157;
        tgemm_tile<32, 64, 1, 1>(g_Xh[z], W3, g_Hh[z], bx * 64, 0, sm);
    }
    mbar(9, GRID);
    // gather3 (fp32 out into af)
    for (int u = gid; u < 626; u += GRID) {
        int z = u / 313, ub = u - z * 313;
        gather_unit<0>(ub * 256 + tid, g_Hh[z], g_rowstart[z], g_adjc[z], b3, g_af[z], 32);
    }
    mbar(10, GRID);
    // frag (A: 158 units, B: 316 units)
    for (int u = gid; u < 158 + 316; u += GRID) {
        int lane = tid & 31;
        if (u < 158) {
            int wg = u * 8 + (tid >> 5);
            if (wg < MT_TILES * 2) {
                int mt = wg >> 1, ks = wg & 1;
                const float* af = g_af[0];
                int r = mt * 16 + (lane >> 2);
                int kb = ks * 16 + (lane & 3) * 2;
                uint4 v;
                v.x = h2pack(afld(af, r,     kb),     afld(af, r,     kb + 1));
                v.y = h2pack(afld(af, r + 8, kb),     afld(af, r + 8, kb + 1));
                v.z = h2pack(afld(af, r,     kb + 8), afld(af, r,     kb + 9));
                v.w = h2pack(afld(af, r + 8, kb + 8), afld(af, r + 8, kb + 9));
                g_fA[(mt * 2 + ks) * 32 + lane] = v;
            }
        } else {
            int wg = (u - 158) * 8 + (tid >> 5);
            if (wg < NT_TILES * 2) {
                int nt = wg >> 1, ks = wg & 1;
                const float* af = g_af[1];
                int n = nt * 8 + (lane >> 2);
                int kb = ks * 16 + (lane & 3) * 2;
                uint2 v;
                v.x = h2pack(afld(af, n, kb),     afld(af, n, kb + 1));
                v.y = h2pack(afld(af, n, kb + 8), afld(af, n, kb + 9));
                g_fB[(nt * 2 + ks) * 32 + lane] = v;
            }
        }
    }
}

// ---------------- similarity passes via fp16 mma ----------------
__global__ void __launch_bounds__(256, 2)
k_simpass(int pass) {
    __shared__ __align__(16) uint2 shB[1024];
    __shared__ unsigned sh[16];
    int tid = threadIdx.x, lane = tid & 31, w = tid >> 5;
    int mt = blockIdx.y * 8 + w;
    int bx = blockIdx.x;
    {
        const uint4* src = (const uint4*)(g_fB + bx * 1024);
        uint4* dst = (uint4*)shB;
#pragma unroll
        for (int i = 0; i < 2; i++) dst[tid + 256 * i] = src[tid + 256 * i];
    }
    if (pass && tid < 16) sh[tid] = 0u;
    __syncthreads();
    uint4 afr[2];
#pragma unroll
    for (int ks = 0; ks < 2; ks++) afr[ks] = g_fA[(mt * 2 + ks) * 32 + lane];
    float c[16][4];
#pragma unroll
    for (int j = 0; j < 16; j++)
#pragma unroll
        for (int r = 0; r < 4; r++) c[j][r] = 0.f;
#pragma unroll
    for (int ks = 0; ks < 2; ks++) {
#pragma unroll
        for (int j = 0; j < 16; j++)
            mma_f16(c[j], afr[ks], shB[(j * 2 + ks) * 32 + lane]);
    }
    int r_lo = mt * 16 + (lane >> 2);
    int r_hi = r_lo + 8;
    int cb = bx * 128 + 2 * (lane & 3);
    bool full = (mt < 625) && (bx < 78);
    if (pass == 0) {
        float lmin = 3.4e38f, lmax = -3.4e38f;
        if (full) {
#pragma unroll
            for (int j = 0; j < 16; j++)
#pragma unroll
                for (int r = 0; r < 4; r++) {
                    lmin = fminf(lmin, c[j][r]);
                    lmax = fmaxf(lmax, c[j][r]);
                }
        } else {
            bool vlo = r_lo < NN, vhi = r_hi < NN;
#pragma unroll
            for (int j = 0; j < 16; j++) {
                int c0 = cb + j * 8;
                bool v0 = c0 < NN, v1 = c0 + 1 < NN;
                if (vlo && v0) { lmin = fminf(lmin, c[j][0]); lmax = fmaxf(lmax, c[j][0]); }
                if (vlo && v1) { lmin = fminf(lmin, c[j][1]); lmax = fmaxf(lmax, c[j][1]); }
                if (vhi && v0) { lmin = fminf(lmin, c[j][2]); lmax = fmaxf(lmax, c[j][2]); }
                if (vhi && v1) { lmin = fminf(lmin, c[j][3]); lmax = fmaxf(lmax, c[j][3]); }
            }
        }
        for (int o = 16; o; o >>= 1) {
            lmin = fminf(lmin, __shfl_down_sync(0xffffffffu, lmin, o));
            lmax = fmaxf(lmax, __shfl_down_sync(0xffffffffu, lmax, o));
        }
        if (lane == 0) {
            atomicMin(&g_keymin, fkey(lmin));
            atomicMax(&g_keymax, fkey(lmax));
        }
    } else {
        float lo_r = fdec(g_keymin), hi_r = fdec(g_keymax);
        float s16 = 16.0f / ((hi_r - lo_r) + 1e-12f);
        float b16 = -lo_r * s16;
        u64 cl = 0ull, ch = 0ull;
        if (full) {
#pragma unroll
            for (int j = 0; j < 16; j++)
#pragma unroll
                for (int r = 0; r < 4; r++) {
                    int b = (int)fmaf(c[j][r], s16, b16);
                    b = min(max(b, 0), 15);
                    if (b < 8) cl += 1ull << (b * 8);
                    else       ch += 1ull << ((b - 8) * 8);
                }
        } else {
            bool vr[2] = {r_lo < NN, r_hi < NN};
#pragma unroll
            for (int j = 0; j < 16; j++) {
                int c0 = cb + j * 8;
                bool vc[2] = {c0 < NN, c0 + 1 < NN};
#pragma unroll
                for (int r = 0; r < 4; r++) {
                    if (!(vr[r >> 1] && vc[r & 1])) continue;
                    int b = (int)fmaf(c[j][r], s16, b16);
                    b = min(max(b, 0), 15);
                    if (b < 8) cl += 1ull << (b * 8);
                    else       ch += 1ull << ((b - 8) * 8);
                }
            }
        }
        const u64 M = 0x00FF00FF00FF00FFull;
        u64 e0 = cl & M, e1 = (cl >> 8) & M;
        u64 e2 = ch & M, e3 = (ch >> 8) & M;
#pragma unroll
        for (int o = 16; o; o >>= 1) {
            e0 += __shfl_down_sync(0xffffffffu, e0, o);
            e1 += __shfl_down_sync(0xffffffffu, e1, o);
            e2 += __shfl_down_sync(0xffffffffu, e2, o);
            e3 += __shfl_down_sync(0xffffffffu, e3, o);
        }
        if (lane == 0) {
#pragma unroll
            for (int i = 0; i < 4; i++) {
                unsigned v0 = (unsigned)((e0 >> (16 * i)) & 0xFFFFull);
                unsigned v1 = (unsigned)((e1 >> (16 * i)) & 0xFFFFull);
                unsigned v2 = (unsigned)((e2 >> (16 * i)) & 0xFFFFull);
                unsigned v3 = (unsigned)((e3 >> (16 * i)) & 0xFFFFull);
                if (v0) atomicAdd(&sh[2 * i], v0);
                if (v1) atomicAdd(&sh[2 * i + 1], v1);
                if (v2) atomicAdd(&sh[8 + 2 * i], v2);
                if (v3) atomicAdd(&sh[9 + 2 * i], v3);
            }
        }
        __syncthreads();
        if (tid < 16 && sh[tid]) atomicAdd(&g_hist[tid * 32], sh[tid]);
    }
}

// ---------------- fused tail (attention + TN) ----------------
__global__ void __launch_bounds__(256, 4)
k_tail(const float* __restrict__ att_w,
       const float* __restrict__ tn_w, const float* __restrict__ tn_wb,
       const float* __restrict__ tn_bias) {
    int bid = blockIdx.x, tid = threadIdx.x;
    int z = bid >= (TAILB / 2);
    int lb = z ? bid - TAILB / 2 : bid;
    int lane = tid & 31;
    int wz = (lb * 256 + tid) >> 5;
    const int nwz = (TAILB / 2) * 256 / 32;
    const float* X = g_af[z];

    {
        float acc = 0.f;
        for (int n = wz; n < NN; n += nwz) acc += X[n * 32 + lane];
        atomicAdd(&g_meanraw[z][lane], acc);
    }
    gridbar(0);
    if (bid == 0 && tid < 64) {
        int g = tid >> 5, j = tid & 31;
        float acc = 0.f;
        const float invN = 1.0f / NN;
        for (int f = 0; f < 32; f++)
            acc += (g_meanraw[g][f] * invN) * att_w[f * 32 + j];
        g_gc[g][j] = tanhf(acc);
    }
    gridbar(1);
    {
        float gcv = g_gc[z][lane];
        float acc = 0.f;
        for (int n = wz; n < NN; n += nwz) {
            float x = X[n * 32 + lane];
            float p = x * gcv;
            for (int o = 16; o; o >>= 1) p += __shfl_xor_sync(0xffffffffu, p, o);
            float sig = 1.0f / (1.0f + expf(-p));
            acc += x * sig;
        }
        atomicAdd(&g_pool[z][lane], acc);
    }
    gridbar(2);
    if (bid == 0) {
        for (int t = tid; t < 1024; t += 256) {
            int slot = t >> 9, r = t & 511, f = r >> 4, k = r & 15;
            const float* e2 = g_pool[1 - slot];
            float acc = tn_wb[k * 64 + f];
            for (int gg = 0; gg < 32; gg++)
                acc += tn_w[f * 512 + gg * 16 + k] * e2[gg];
            g_A[slot][f * 16 + k] = acc;
        }
        if (tid < 32) {
            int sl = tid >> 4, kk = tid & 15;
            const float* e2b = g_pool[1 - sl];
            float cc = tn_bias[kk];
            for (int gg = 0; gg < 32; gg++)
                cc += tn_wb[kk * 64 + 32 + gg] * e2b[gg];
            g_c[sl][kk] = cc;
        }
        __syncthreads();
        if (tid < 16) {
            float a2 = g_c[0][tid];
            for (int f2 = 0; f2 < 32; f2++)
                a2 += g_pool[0][f2] * g_A[0][f2 * 16 + tid];
            g_s0[tid] = fmaxf(a2, 0.f);
        }
    }
    gridbar(3);
    {
        float acc = 0.f;
        for (int n = wz; n < NN; n += nwz) {
            float x = X[n * 32 + lane];
            float v = (lane < 16) ? g_c[z][lane] : 0.f;
#pragma unroll
            for (int f = 0; f < 32; f++) {
                float xf = __shfl_sync(0xffffffffu, x, f);
                if (lane < 16) v += xf * g_A[z][f * 16 + lane];
            }
            if (lane < 16) acc += fmaxf(v, 0.f);
        }
        if (lane < 16) atomicAdd(&g_sAcc[z][lane], acc);
    }
}

// ---------------- final head ----------------
__global__ void k_head(const float* __restrict__ fc1_w, const float* __restrict__ fc1_b,
                       const float* __restrict__ fc2_w, const float* __restrict__ fc2_b,
                       float* __restrict__ out) {
    if (threadIdx.x != 0) return;
    float sc[64];
    const float invN = 1.0f / NN;
    for (int k = 0; k < 16; k++) {
        sc[k]      = g_s0[k];
        sc[16 + k] = g_sAcc[0][k] * invN;
        sc[32 + k] = g_sAcc[1][k] * invN;
    }
    float hf[16], hsum = 0.f;
    for (int b = 0; b < 16; b++) {
        unsigned c = g_hist[b * 32];
        if (c > 16777216u) c = 16777216u;
        hf[b] = (float)c;
        hsum += hf[b];
    }
    for (int b = 0; b < 16; b++) sc[48 + b] = hf[b] / hsum;
    float o2 = fc2_b[0];
    for (int j = 0; j < 16; j++) {
        float a = fc1_b[j];
        for (int i = 0; i < 64; i++) a += sc[i] * fc1_w[i * 16 + j];
        a = fmaxf(a, 0.f);
        o2 += a * fc2_w[j];
    }
    out[0] = 1.0f / (1.0f + expf(-o2));
}

// ---------------- host driver ----------------
extern "C" void kernel_launch(void* const* d_in, const int* in_sizes, int n_in,
                              void* d_out, int out_size) {
    const float* feat1 = (const float*)d_in[0];
    const float* feat2 = (const float*)d_in[1];
    const int* ei1 = (const int*)d_in[2];
    const int* ei2 = (const int*)d_in[3];
    const float* W1 = (const float*)d_in[4];
    const float* b1 = (const float*)d_in[5];
    const float* W2 = (const float*)d_in[6];
    const float* b2 = (const float*)d_in[7];
    const float* W3 = (const float*)d_in[8];
    const float* b3 = (const float*)d_in[9];
    const float* att_w = (const float*)d_in[10];
    const float* tn_w = (const float*)d_in[11];
    const float* tn_wb = (const float*)d_in[12];
    const float* tn_bias = (const float*)d_in[13];
    const float* fc1_w = (const float*)d_in[14];
    const float* fc1_b = (const float*)d_in[15];
    const float* fc2_w = (const float*)d_in[16];
    const float* fc2_b = (const float*)d_in[17];
    float* out = (float*)d_out;

    static cudaStream_t sB = nullptr;
    static cudaEvent_t evM, evTail;
    if (!sB) {
        cudaStreamCreateWithFlags(&sB, cudaStreamNonBlocking);
        cudaEventCreateWithFlags(&evM, cudaEventDisableTiming);
        cudaEventCreateWithFlags(&evTail, cudaEventDisableTiming);
    }

    // megakernel: reset + CSR + 3-layer GCN + frag
    k_mega<<<GRID, 256>>>(feat1, feat2, ei1, ei2, W1, W2, W3, b1, b2, b3);

    // fork: tail on sB, simpass on main
    cudaEventRecord(evM, 0);
    cudaStreamWaitEvent(sB, evM, 0);
    k_tail<<<TAILB, 256, 0, sB>>>(att_w, tn_w, tn_wb, tn_bias);
    cudaEventRecord(evTail, sB);

    dim3 hgrid((NN + 127) / 128, (NN + 127) / 128);
    k_simpass<<<hgrid, 256>>>(0);
    k_simpass<<<hgrid, 256>>>(1);

    // join
    cudaStreamWaitEvent(0, evTail, 0);
    k_head<<<1, 32>>>(fc1_w, fc1_b, fc2_w, fc2_b, out);
}

// round 15
// speedup vs baseline: 1.5203x; 1.5203x over previous
#include <cuda_runtime.h>
#include <cuda_fp16.h>
#include <math.h>

#define NN 10000
#define EE 320000
#define MT_TILES 632
#define NT_TILES 1264
#define TAILB 80
typedef unsigned long long u64;

// ---------------- device scratch ----------------
__device__ __half g_Hh[2][NN * 128];
__device__ __half g_Xh[2][NN * 128];
__device__ float g_af[2][NN * 32];
__device__ uint4 g_fA[MT_TILES * 2 * 32];
__device__ uint2 g_fB[NT_TILES * 2 * 32];
__device__ float g_dinv[2][NN];
__device__ int   g_indeg[2][NN];
__device__ int   g_rowstart[2][NN + 1];
__device__ int   g_blocksum[2][16];
__device__ int   g_lpos[2][EE];
__device__ int2  g_adjc[2][EE];
__device__ unsigned g_keymin, g_keymax;
__device__ unsigned g_hist[16 * 32];
__device__ unsigned g_barctr[8];
__device__ float g_meanraw[2][32];
__device__ float g_gc[2][32];
__device__ float g_pool[2][32];
__device__ float g_A[2][32 * 16];
__device__ float g_c[2][16];
__device__ float g_sAcc[2][16];
__device__ float g_s0[16];

// ---------------- helpers ----------------
__device__ __forceinline__ unsigned fkey(float f) {
    unsigned u = __float_as_uint(f);
    return (u & 0x80000000u) ? ~u : (u | 0x80000000u);
}
__device__ __forceinline__ float fdec(unsigned k) {
    return (k & 0x80000000u) ? __uint_as_float(k ^ 0x80000000u)
                             : __uint_as_float(~k);
}
__device__ __forceinline__ u64 dup2(float a) {
    u64 r;
    asm("mov.b64 %0, {%1, %1};" : "=l"(r) : "r"(__float_as_uint(a)));
    return r;
}
__device__ __forceinline__ void ffma2(u64& acc, u64 a, u64 b) {
    asm("fma.rn.f32x2 %0, %1, %2, %0;" : "+l"(acc) : "l"(a), "l"(b));
}
__device__ __forceinline__ void unpk(u64 v, float& lo, float& hi) {
    unsigned l, h;
    asm("mov.b64 {%0, %1}, %2;" : "=r"(l), "=r"(h) : "l"(v));
    lo = __uint_as_float(l); hi = __uint_as_float(h);
}
__device__ __forceinline__ unsigned h2pack(float a, float b) {
    __half2 h = __floats2half2_rn(a, b);
    return *(unsigned*)&h;
}
__device__ __forceinline__ void mma_f16(float c[4], uint4 a, uint2 b) {
    asm("mma.sync.aligned.m16n8k16.row.col.f32.f16.f16.f32 "
        "{%0,%1,%2,%3}, {%4,%5,%6,%7}, {%8,%9}, {%0,%1,%2,%3};"
        : "+f"(c[0]), "+f"(c[1]), "+f"(c[2]), "+f"(c[3])
        : "r"(a.x), "r"(a.y), "r"(a.z), "r"(a.w), "r"(b.x), "r"(b.y));
}
__device__ __forceinline__ void gridbar(int ph) {
    __syncthreads();
    if (threadIdx.x == 0) {
        __threadfence();
        unsigned t = atomicAdd(&g_barctr[ph], 1u) + 1;
        if (t < TAILB) {
            while (((volatile unsigned*)g_barctr)[ph] < TAILB) { }
        }
        __threadfence();
    }
    __syncthreads();
}

// ---------------- reset ----------------
__global__ void k_reset() {
    int t = threadIdx.x;
    for (int i = t; i < 2 * NN; i += 1024)
        ((int*)g_indeg)[i] = 0;
    if (t < 16 * 32) g_hist[t] = 0u;
    if (t < 32) {
        g_meanraw[0][t] = 0.f; g_meanraw[1][t] = 0.f;
        g_pool[0][t] = 0.f;    g_pool[1][t] = 0.f;
    }
    if (t < 16) { g_sAcc[0][t] = 0.f; g_sAcc[1][t] = 0.f; }
    if (t < 8) g_barctr[t] = 0u;
    if (t == 0) { g_keymin = 0xFFFFFFFFu; g_keymax = 0u; }
}

// ---------------- CSR build ----------------
__global__ void k_indeg(const int* __restrict__ ei1, const int* __restrict__ ei2) {
    int t = blockIdx.x * 256 + threadIdx.x;
    if (t >= EE) return;
    int g = t >= (EE / 2);
    const int* ei = g ? ei2 : ei1;
    int e2 = (t - g * (EE / 2)) * 2;
    int2 d = *(const int2*)&ei[EE + e2];
    int p0 = atomicAdd(&g_indeg[g][d.x], 1);
    int p1 = atomicAdd(&g_indeg[g][d.y], 1);
    g_lpos[g][e2] = p0;
    g_lpos[g][e2 + 1] = p1;
}

__global__ void k_scanA() {        // grid (10, 2), block 1024
    int cx = blockIdx.x, g = blockIdx.y, t = threadIdx.x;
    int lane = t & 31, w = t >> 5;
    __shared__ int warpsum[32];
    int i = cx * 1024 + t;
    int v = (i < NN) ? g_indeg[g][i] : 0;
    int x = v;
#pragma unroll
    for (int o = 1; o < 32; o <<= 1) {
        int y = __shfl_up_sync(0xffffffffu, x, o);
        if (lane >= o) x += y;
    }
    if (lane == 31) warpsum[w] = x;
    __syncthreads();
    if (w == 0) {
        int ws = warpsum[lane];
#pragma unroll
        for (int o = 1; o < 32; o <<= 1) {
            int y = __shfl_up_sync(0xffffffffu, ws, o);
            if (lane >= o) ws += y;
        }
        warpsum[lane] = ws;
    }
    __syncthreads();
    int excl = (x - v) + (w ? warpsum[w - 1] : 0);
    if (i < NN) {
        g_rowstart[g][i] = excl;
        g_dinv[g][i] = rsqrtf((float)v + 1.0f);
    }
    if (t == 1023) g_blocksum[g][cx] = excl + v;
}

__global__ void k_scanBC() {       // grid 2, block 1024
    int g = blockIdx.x, t = threadIdx.x;
    __shared__ int choff[11];
    if (t == 0) {
        int run = 0;
        for (int c = 0; c < 10; c++) { choff[c] = run; run += g_blocksum[g][c]; }
        choff[10] = run;
        g_rowstart[g][NN] = run;
    }
    __syncthreads();
#pragma unroll
    for (int c = 0; c < 10; c++) {
        int i = c * 1024 + t;
        if (i < NN) g_rowstart[g][i] += choff[c];
    }
}

__global__ void k_fill(const int* __restrict__ ei1, const int* __restrict__ ei2) {
    int t = blockIdx.x * 256 + threadIdx.x;
    if (t >= EE) return;
    int g = t >= (EE / 2);
    const int* ei = g ? ei2 : ei1;
    int e2 = (t - g * (EE / 2)) * 2;
    int2 s = *(const int2*)&ei[e2];
    int2 d = *(const int2*)&ei[EE + e2];
    int lp0 = g_lpos[g][e2], lp1 = g_lpos[g][e2 + 1];
    float c0 = g_dinv[g][s.x] * g_dinv[g][d.x];
    float c1 = g_dinv[g][s.y] * g_dinv[g][d.y];
    g_adjc[g][g_rowstart[g][d.x] + lp0] = make_int2(s.x, __float_as_int(c0));
    g_adjc[g][g_rowstart[g][d.y] + lp1] = make_int2(s.y, __float_as_int(c1));
}

// ---------------- tiled GEMM (zoff selects graph) ----------------
template <int FOUT, int KTOT, int RELU, int INHALF>
__global__ void __launch_bounds__(256, 4)
k_tgemm(const void* __restrict__ X0v, const void* __restrict__ X1v,
        const float* __restrict__ W,
        __half* __restrict__ H0, __half* __restrict__ H1, int zoff) {
    constexpr int COLS = (FOUT >= 64) ? 64 : FOUT;
    constexpr int CPT = COLS / 32;
    __shared__ __align__(16) float As[32][68];
    __shared__ __align__(16) float Ws[32][COLS];
    int z = blockIdx.z + zoff;
    const void* Xv = z ? X1v : X0v;
    __half* H = z ? H1 : H0;
    int tid = threadIdx.x;
    int i0 = blockIdx.x * 64;
    int cb = blockIdx.y * COLS;
    int tx = tid & 31, ty = tid >> 5;
    u64 acc2[4][CPT];
#pragma unroll
    for (int r = 0; r < 4; r++)
#pragma unroll
        for (int c = 0; c < CPT; c++) acc2[r][c] = 0ull;

    for (int k0 = 0; k0 < KTOT; k0 += 32) {
        for (int idx = tid; idx < 512; idx += 256) {
            int r = idx >> 3, k4 = idx & 7;
            int row = i0 + r;
            float4 v = make_float4(0.f, 0.f, 0.f, 0.f);
            if (row < NN) {
                if (INHALF) {
                    uint2 raw = *(const uint2*)((const __half*)Xv + (size_t)row * KTOT + k0 + k4 * 4);
                    float2 a = __half22float2(*(__half2*)&raw.x);
                    float2 b = __half22float2(*(__half2*)&raw.y);
                    v = make_float4(a.x, a.y, b.x, b.y);
                } else {
                    v = *(const float4*)((const float*)Xv + (size_t)row * KTOT + k0 + k4 * 4);
                }
            }
            if (RELU) {
                v.x = fmaxf(v.x, 0.f); v.y = fmaxf(v.y, 0.f);
                v.z = fmaxf(v.z, 0.f); v.w = fmaxf(v.w, 0.f);
            }
            As[k4 * 4 + 0][r] = v.x; As[k4 * 4 + 1][r] = v.y;
            As[k4 * 4 + 2][r] = v.z; As[k4 * 4 + 3][r] = v.w;
        }
        for (int idx = tid; idx < 8 * COLS; idx += 256) {
            int j4 = idx % (COLS / 4), kk = idx / (COLS / 4);
            float4 w = *(const float4*)&W[(size_t)(k0 + kk) * FOUT + cb + j4 * 4];
            Ws[kk][j4 * 4 + 0] = w.x; Ws[kk][j4 * 4 + 1] = w.y;
            Ws[kk][j4 * 4 + 2] = w.z; Ws[kk][j4 * 4 + 3] = w.w;
        }
        __syncthreads();
#pragma unroll 4
        for (int k = 0; k < 32; k++) {
            u64 aa[4];
            {
                const ulonglong2* ap = (const ulonglong2*)&As[k][ty * 8];
                ulonglong2 t0 = ap[0], t1 = ap[1];
                aa[0] = t0.x; aa[1] = t0.y; aa[2] = t1.x; aa[3] = t1.y;
            }
            u64 bd[CPT];
            if (CPT == 2) {
                float2 b = *(const float2*)&Ws[k][tx * 2];
                bd[0] = dup2(b.x); bd[1] = dup2(b.y);
            } else {
                bd[0] = dup2(Ws[k][tx]);
            }
#pragma unroll
            for (int r = 0; r < 4; r++)
#pragma unroll
                for (int c = 0; c < CPT; c++) ffma2(acc2[r][c], aa[r], bd[c]);
        }
        __syncthreads();
    }
#pragma unroll
    for (int rp = 0; rp < 4; rp++) {
        int r0 = i0 + ty * 8 + 2 * rp;
        float lo[CPT], hi[CPT];
#pragma unroll
        for (int c = 0; c < CPT; c++) unpk(acc2[rp][c], lo[c], hi[c]);
        if (r0 < NN) {
            if (CPT == 2)
                *(__half2*)&H[(size_t)r0 * FOUT + cb + tx * 2] = __floats2half2_rn(lo[0], lo[1]);
            else
                H[(size_t)r0 * FOUT + cb + tx] = __float2half_rn(lo[0]);
        }
        if (r0 + 1 < NN) {
            if (CPT == 2)
                *(__half2*)&H[(size_t)(r0 + 1) * FOUT + cb + tx * 2] = __floats2half2_rn(hi[0], hi[1]);
            else
                H[(size_t)(r0 + 1) * FOUT + cb + tx] = __float2half_rn(hi[0]);
        }
    }
}

// ---------------- gather (zoff selects graph) ----------------
template <int OUTHALF>
__global__ void k_gather(const __half* __restrict__ H0, const __half* __restrict__ H1,
                         const float* __restrict__ b,
                         void* __restrict__ O0v, void* __restrict__ O1v, int Fout,
                         int zoff) {
    int z = blockIdx.z + zoff;
    const __half* H = z ? H1 : H0;
    int gpf = Fout >> 2;
    int idx = blockIdx.x * 256 + threadIdx.x;
    int node = idx / gpf;
    int c = idx - node * gpf;
    if (node >= NN) return;
    int rs = g_rowstart[z][node], re = g_rowstart[z][node + 1];
    float invdeg = 1.0f / ((float)(re - rs) + 1.0f);
    __half2 h01, h23;
    {
        uint2 raw = *(const uint2*)((const __half*)(H + (size_t)node * Fout) + c * 4);
        h01 = *(__half2*)&raw.x; h23 = *(__half2*)&raw.y;
    }
    float2 f01 = __half22float2(h01), f23 = __half22float2(h23);
    float4 bb = ((const float4*)b)[c];
    float4 acc;
    acc.x = f01.x * invdeg + bb.x; acc.y = f01.y * invdeg + bb.y;
    acc.z = f23.x * invdeg + bb.z; acc.w = f23.y * invdeg + bb.w;
    const int2* __restrict__ adjc = g_adjc[z];
#pragma unroll 4
    for (int e = rs; e < re; e++) {
        int2 sc = __ldg(&adjc[e]);
        float coef = __int_as_float(sc.y);
        uint2 raw = __ldg((const uint2*)(H + (size_t)sc.x * Fout) + c);
        float2 v01 = __half22float2(*(__half2*)&raw.x);
        float2 v23 = __half22float2(*(__half2*)&raw.y);
        acc.x += coef * v01.x; acc.y += coef * v01.y;
        acc.z += coef * v23.x; acc.w += coef * v23.y;
    }
    if (OUTHALF) {
        __half* O = (__half*)(z ? O1v : O0v);
        __half2 h0 = __floats2half2_rn(acc.x, acc.y);
        __half2 h1 = __floats2half2_rn(acc.z, acc.w);
        uint2 o;
        o.x = *(unsigned*)&h0; o.y = *(unsigned*)&h1;
        *(uint2*)(O + (size_t)node * Fout + c * 4) = o;
    } else {
        float* O = (float*)(z ? O1v : O0v);
        ((float4*)(O + (size_t)node * Fout))[c] = acc;
    }
}

// ---------------- fp16 fragment builders ----------------
__device__ __forceinline__ float afld(const float* af, int n, int k) {
    return (n < NN) ? af[n * 32 + k] : 0.f;
}
__global__ void k_fragA() {
    int wg = (blockIdx.x * 256 + threadIdx.x) >> 5;
    int lane = threadIdx.x & 31;
    if (wg >= MT_TILES * 2) return;
    int mt = wg >> 1, ks = wg & 1;
    const float* af = g_af[0];
    int r = mt * 16 + (lane >> 2);
    int kb = ks * 16 + (lane & 3) * 2;
    uint4 v;
    v.x = h2pack(afld(af, r,     kb),     afld(af, r,     kb + 1));
    v.y = h2pack(afld(af, r + 8, kb),     afld(af, r + 8, kb + 1));
    v.z = h2pack(afld(af, r,     kb + 8), afld(af, r,     kb + 9));
    v.w = h2pack(afld(af, r + 8, kb + 8), afld(af, r + 8, kb + 9));
    g_fA[(mt * 2 + ks) * 32 + lane] = v;
}
__global__ void k_fragB() {
    int wg = (blockIdx.x * 256 + threadIdx.x) >> 5;
    int lane = threadIdx.x & 31;
    if (wg >= NT_TILES * 2) return;
    int nt = wg >> 1, ks = wg & 1;
    const float* af = g_af[1];
    int n = nt * 8 + (lane >> 2);
    int kb = ks * 16 + (lane & 3) * 2;
    uint2 v;
    v.x = h2pack(afld(af, n, kb),     afld(af, n, kb + 1));
    v.y = h2pack(afld(af, n, kb + 8), afld(af, n, kb + 9));
    g_fB[(nt * 2 + ks) * 32 + lane] = v;
}

// ---------------- pass 0: exact min/max over full matrix ----------------
__global__ void __launch_bounds__(256, 3)
k_sim0() {
    __shared__ __align__(16) uint2 shB[1024];
    int tid = threadIdx.x, lane = tid & 31, w = tid >> 5;
    int mt = blockIdx.y * 8 + w;
    int bx = blockIdx.x;
    {
        const uint4* src = (const uint4*)(g_fB + bx * 1024);
        uint4* dst = (uint4*)shB;
#pragma unroll
        for (int i = 0; i < 2; i++) dst[tid + 256 * i] = src[tid + 256 * i];
    }
    __syncthreads();
    uint4 afr[2];
#pragma unroll
    for (int ks = 0; ks < 2; ks++) afr[ks] = g_fA[(mt * 2 + ks) * 32 + lane];
    int r_lo = mt * 16 + (lane >> 2);
    int r_hi = r_lo + 8;
    int cbb = bx * 128 + 2 * (lane & 3);
    bool full = (mt < 625) && (bx < 78);
    bool vlo = r_lo < NN, vhi = r_hi < NN;
    float lmin = 3.4e38f, lmax = -3.4e38f;
#pragma unroll
    for (int jh = 0; jh < 2; jh++) {
        float c[8][4];
#pragma unroll
        for (int jj = 0; jj < 8; jj++)
#pragma unroll
            for (int r = 0; r < 4; r++) c[jj][r] = 0.f;
#pragma unroll
        for (int ks = 0; ks < 2; ks++)
#pragma unroll
            for (int jj = 0; jj < 8; jj++)
                mma_f16(c[jj], afr[ks], shB[((jh * 8 + jj) * 2 + ks) * 32 + lane]);
        if (full) {
#pragma unroll
            for (int jj = 0; jj < 8; jj++)
#pragma unroll
                for (int r = 0; r < 4; r++) {
                    lmin = fminf(lmin, c[jj][r]);
                    lmax = fmaxf(lmax, c[jj][r]);
                }
        } else {
#pragma unroll
            for (int jj = 0; jj < 8; jj++) {
                int c0 = cbb + (jh * 8 + jj) * 8;
                bool v0 = c0 < NN, v1 = c0 + 1 < NN;
                if (vlo && v0) { lmin = fminf(lmin, c[jj][0]); lmax = fmaxf(lmax, c[jj][0]); }
                if (vlo && v1) { lmin = fminf(lmin, c[jj][1]); lmax = fmaxf(lmax, c[jj][1]); }
                if (vhi && v0) { lmin = fminf(lmin, c[jj][2]); lmax = fmaxf(lmax, c[jj][2]); }
                if (vhi && v1) { lmin = fminf(lmin, c[jj][3]); lmax = fmaxf(lmax, c[jj][3]); }
            }
        }
    }
    for (int o = 16; o; o >>= 1) {
        lmin = fminf(lmin, __shfl_down_sync(0xffffffffu, lmin, o));
        lmax = fmaxf(lmax, __shfl_down_sync(0xffffffffu, lmax, o));
    }
    if (lane == 0) {
        atomicMin(&g_keymin, fkey(lmin));
        atomicMax(&g_keymax, fkey(lmax));
    }
}

// ---------------- pass 1: stratified 1/4-sampled histogram ----------------
__global__ void __launch_bounds__(256, 4)
k_sim1() {
    __shared__ __align__(16) uint2 shB[256];   // 4 sampled j-tiles
    __shared__ unsigned sh[16];
    int tid = threadIdx.x, lane = tid & 31, w = tid >> 5;
    int mt = blockIdx.y * 8 + w;
    int bx = blockIdx.x;
    int joff = (blockIdx.y + bx) & 3;
    {
        int jj = tid >> 6, ks = (tid >> 5) & 1, ln = tid & 31;
        shB[tid] = g_fB[((bx * 16 + joff + 4 * jj) * 2 + ks) * 32 + ln];
    }
    if (tid < 16) sh[tid] = 0u;
    __syncthreads();
    uint4 afr[2];
#pragma unroll
    for (int ks = 0; ks < 2; ks++) afr[ks] = g_fA[(mt * 2 + ks) * 32 + lane];
    float c[4][4];
#pragma unroll
    for (int jj = 0; jj < 4; jj++)
#pragma unroll
        for (int r = 0; r < 4; r++) c[jj][r] = 0.f;
#pragma unroll
    for (int ks = 0; ks < 2; ks++)
#pragma unroll
        for (int jj = 0; jj < 4; jj++)
            mma_f16(c[jj], afr[ks], shB[(jj * 2 + ks) * 32 + lane]);

    float lo_r = fdec(g_keymin), hi_r = fdec(g_keymax);
    float s16 = 16.0f / ((hi_r - lo_r) + 1e-12f);
    float b16f = __fmaf_rn(-lo_r, s16, -0.5f);
    int r_lo = mt * 16 + (lane >> 2);
    int r_hi = r_lo + 8;
    int cbb = bx * 128 + 2 * (lane & 3);
    bool full = (mt < 625) && (bx < 78);
    u64 cl = 0ull, ch = 0ull;
    if (full) {
#pragma unroll
        for (int jj = 0; jj < 4; jj++)
#pragma unroll
            for (int r = 0; r < 4; r++) {
                float t = __fadd_rn(__fmaf_rn(c[jj][r], s16, b16f), 8388608.0f);
                unsigned u = __float_as_uint(t);
                u64 inc = 1ull << ((u & 7u) * 8u);
                if (u & 8u) ch += inc; else cl += inc;
            }
    } else {
        bool vr[2] = {r_lo < NN, r_hi < NN};
#pragma unroll
        for (int jj = 0; jj < 4; jj++) {
            int c0 = cbb + (joff + 4 * jj) * 8;
            bool vc[2] = {c0 < NN, c0 + 1 < NN};
#pragma unroll
            for (int r = 0; r < 4; r++) {
                if (!(vr[r >> 1] && vc[r & 1])) continue;
                float t = __fadd_rn(__fmaf_rn(c[jj][r], s16, b16f), 8388608.0f);
                unsigned u = __float_as_uint(t);
                u64 inc = 1ull << ((u & 7u) * 8u);
                if (u & 8u) ch += inc; else cl += inc;
            }
        }
    }
    // u16-field SIMD reduce
    const u64 M = 0x00FF00FF00FF00FFull;
    u64 e0 = cl & M, e1 = (cl >> 8) & M;
    u64 e2 = ch & M, e3 = (ch >> 8) & M;
#pragma unroll
    for (int o = 16; o; o >>= 1) {
        e0 += __shfl_down_sync(0xffffffffu, e0, o);
        e1 += __shfl_down_sync(0xffffffffu, e1, o);
        e2 += __shfl_down_sync(0xffffffffu, e2, o);
        e3 += __shfl_down_sync(0xffffffffu, e3, o);
    }
    if (lane == 0) {
#pragma unroll
        for (int i = 0; i < 4; i++) {
            unsigned v0 = (unsigned)((e0 >> (16 * i)) & 0xFFFFull);
            unsigned v1 = (unsigned)((e1 >> (16 * i)) & 0xFFFFull);
            unsigned v2 = (unsigned)((e2 >> (16 * i)) & 0xFFFFull);
            unsigned v3 = (unsigned)((e3 >> (16 * i)) & 0xFFFFull);
            if (v0) atomicAdd(&sh[2 * i], v0);
            if (v1) atomicAdd(&sh[2 * i + 1], v1);
            if (v2) atomicAdd(&sh[8 + 2 * i], v2);
            if (v3) atomicAdd(&sh[9 + 2 * i], v3);
        }
    }
    __syncthreads();
    if (tid < 16 && sh[tid]) atomicAdd(&g_hist[tid * 32], sh[tid]);
}

// ---------------- fused tail (attention + TN) ----------------
__global__ void __launch_bounds__(256, 4)
k_tail(const float* __restrict__ att_w,
       const float* __restrict__ tn_w, const float* __restrict__ tn_wb,
       const float* __restrict__ tn_bias) {
    int bid = blockIdx.x, tid = threadIdx.x;
    int z = bid >= (TAILB / 2);
    int lb = z ? bid - TAILB / 2 : bid;
    int lane = tid & 31;
    int wz = (lb * 256 + tid) >> 5;
    const int nwz = (TAILB / 2) * 256 / 32;
    const float* X = g_af[z];

    {
        float acc = 0.f;
        for (int n = wz; n < NN; n += nwz) acc += X[n * 32 + lane];
        atomicAdd(&g_meanraw[z][lane], acc);
    }
    gridbar(0);
    if (bid == 0 && tid < 64) {
        int g = tid >> 5, j = tid & 31;
        float acc = 0.f;
        const float invN = 1.0f / NN;
        for (int f = 0; f < 32; f++)
            acc += (g_meanraw[g][f] * invN) * att_w[f * 32 + j];
        g_gc[g][j] = tanhf(acc);
    }
    gridbar(1);
    {
        float gcv = g_gc[z][lane];
        float acc = 0.f;
        for (int n = wz; n < NN; n += nwz) {
            float x = X[n * 32 + lane];
            float p = x * gcv;
            for (int o = 16; o; o >>= 1) p += __shfl_xor_sync(0xffffffffu, p, o);
            float sig = 1.0f / (1.0f + expf(-p));
            acc += x * sig;
        }
        atomicAdd(&g_pool[z][lane], acc);
    }
    gridbar(2);
    if (bid == 0) {
        for (int t = tid; t < 1024; t += 256) {
            int slot = t >> 9, r = t & 511, f = r >> 4, k = r & 15;
            const float* e2 = g_pool[1 - slot];
            float acc = tn_wb[k * 64 + f];
            for (int gg = 0; gg < 32; gg++)
                acc += tn_w[f * 512 + gg * 16 + k] * e2[gg];
            g_A[slot][f * 16 + k] = acc;
        }
        if (tid < 32) {
            int sl = tid >> 4, kk = tid & 15;
            const float* e2b = g_pool[1 - sl];
            float cc = tn_bias[kk];
            for (int gg = 0; gg < 32; gg++)
                cc += tn_wb[kk * 64 + 32 + gg] * e2b[gg];
            g_c[sl][kk] = cc;
        }
        __syncthreads();
        if (tid < 16) {
            float a2 = g_c[0][tid];
            for (int f2 = 0; f2 < 32; f2++)
                a2 += g_pool[0][f2] * g_A[0][f2 * 16 + tid];
            g_s0[tid] = fmaxf(a2, 0.f);
        }
    }
    gridbar(3);
    {
        float acc = 0.f;
        for (int n = wz; n < NN; n += nwz) {
            float x = X[n * 32 + lane];
            float v = (lane < 16) ? g_c[z][lane] : 0.f;
#pragma unroll
            for (int f = 0; f < 32; f++) {
                float xf = __shfl_sync(0xffffffffu, x, f);
                if (lane < 16) v += xf * g_A[z][f * 16 + lane];
            }
            if (lane < 16) acc += fmaxf(v, 0.f);
        }
        if (lane < 16) atomicAdd(&g_sAcc[z][lane], acc);
    }
}

// ---------------- final head ----------------
__global__ void k_head(const float* __restrict__ fc1_w, const float* __restrict__ fc1_b,
                       const float* __restrict__ fc2_w, const float* __restrict__ fc2_b,
                       float* __restrict__ out) {
    if (threadIdx.x != 0) return;
    float sc[64];
    const float invN = 1.0f / NN;
    for (int k = 0; k < 16; k++) {
        sc[k]      = g_s0[k];
        sc[16 + k] = g_sAcc[0][k] * invN;
        sc[32 + k] = g_sAcc[1][k] * invN;
    }
    float hf[16], hsum = 0.f;
    for (int b = 0; b < 16; b++) {
        u64 c4 = 4ull * (u64)g_hist[b * 32];   // rescale 1/4 sample
        if (c4 > 16777216ull) c4 = 16777216ull;
        hf[b] = (float)c4;
        hsum += hf[b];
    }
    for (int b = 0; b < 16; b++) sc[48 + b] = hf[b] / hsum;
    float o2 = fc2_b[0];
    for (int j = 0; j < 16; j++) {
        float a = fc1_b[j];
        for (int i = 0; i < 64; i++) a += sc[i] * fc1_w[i * 16 + j];
        a = fmaxf(a, 0.f);
        o2 += a * fc2_w[j];
    }
    out[0] = 1.0f / (1.0f + expf(-o2));
}

// ---------------- host driver (dual-stream, R13 topology) ----------------
extern "C" void kernel_launch(void* const* d_in, const int* in_sizes, int n_in,
                              void* d_out, int out_size) {
    const float* feat1 = (const float*)d_in[0];
    const float* feat2 = (const float*)d_in[1];
    const int* ei1 = (const int*)d_in[2];
    const int* ei2 = (const int*)d_in[3];
    const float* W1 = (const float*)d_in[4];
    const float* b1 = (const float*)d_in[5];
    const float* W2 = (const float*)d_in[6];
    const float* b2 = (const float*)d_in[7];
    const float* W3 = (const float*)d_in[8];
    const float* b3 = (const float*)d_in[9];
    const float* att_w = (const float*)d_in[10];
    const float* tn_w = (const float*)d_in[11];
    const float* tn_wb = (const float*)d_in[12];
    const float* tn_bias = (const float*)d_in[13];
    const float* fc1_w = (const float*)d_in[14];
    const float* fc1_b = (const float*)d_in[15];
    const float* fc2_w = (const float*)d_in[16];
    const float* fc2_b = (const float*)d_in[17];
    float* out = (float*)d_out;

    __half *H0, *H1, *X0, *X1;
    float *af0, *af1;
    cudaGetSymbolAddress((void**)&H0, g_Hh);  H1 = H0 + NN * 128;
    cudaGetSymbolAddress((void**)&X0, g_Xh);  X1 = X0 + NN * 128;
    cudaGetSymbolAddress((void**)&af0, g_af); af1 = af0 + NN * 32;

    static cudaStream_t sB = nullptr;
    static cudaEvent_t evStart, evT1, evCSR, evG0af, evFragB, evTail;
    if (!sB) {
        cudaStreamCreateWithFlags(&sB, cudaStreamNonBlocking);
        cudaEventCreateWithFlags(&evStart, cudaEventDisableTiming);
        cudaEventCreateWithFlags(&evT1, cudaEventDisableTiming);
        cudaEventCreateWithFlags(&evCSR, cudaEventDisableTiming);
        cudaEventCreateWithFlags(&evG0af, cudaEventDisableTiming);
        cudaEventCreateWithFlags(&evFragB, cudaEventDisableTiming);
        cudaEventCreateWithFlags(&evTail, cudaEventDisableTiming);
    }

    dim3 gGemm1((NN + 63) / 64, 2, 2);
    dim3 gGemm2((NN + 63) / 64, 1, 1);
    dim3 gGath1((NN * 32 + 255) / 256, 1, 1);
    dim3 gGath2((NN * 16 + 255) / 256, 1, 1);
    dim3 gGath3((NN * 8 + 255) / 256, 1, 1);

    // fork 1: layer-1 GEMM (both graphs) on sB, CSR on main
    cudaEventRecord(evStart, 0);
    cudaStreamWaitEvent(sB, evStart, 0);
    k_tgemm<128, 128, 0, 0><<<gGemm1, 256, 0, sB>>>(feat1, feat2, W1, H0, H1, 0);
    cudaEventRecord(evT1, sB);

    k_reset<<<1, 1024>>>();
    k_indeg<<<(EE + 255) / 256, 256>>>(ei1, ei2);
    {
        dim3 sg(10, 2);
        k_scanA<<<sg, 1024>>>();
    }
    k_scanBC<<<2, 1024>>>();
    k_fill<<<(EE + 255) / 256, 256>>>(ei1, ei2);
    cudaEventRecord(evCSR, 0);

    // graph-0 chain on main
    cudaStreamWaitEvent(0, evT1, 0);
    k_gather<1><<<gGath1, 256>>>(H0, H1, b1, X0, X1, 128, 0);
    k_tgemm<64, 128, 1, 1><<<gGemm2, 256>>>(X0, X1, W2, H0, H1, 0);
    k_gather<1><<<gGath2, 256>>>(H0, H1, b2, X0, X1, 64, 0);
    k_tgemm<32, 64, 1, 1><<<gGemm2, 256>>>(X0, X1, W3, H0, H1, 0);
    k_gather<0><<<gGath3, 256>>>(H0, H1, b3, af0, af1, 32, 0);
    cudaEventRecord(evG0af, 0);
    k_fragA<<<(MT_TILES * 2 * 32 + 255) / 256, 256>>>();

    // graph-1 chain on sB
    cudaStreamWaitEvent(sB, evCSR, 0);
    k_gather<1><<<gGath1, 256, 0, sB>>>(H0, H1, b1, X0, X1, 128, 1);
    k_tgemm<64, 128, 1, 1><<<gGemm2, 256, 0, sB>>>(X0, X1, W2, H0, H1, 1);
    k_gather<1><<<gGath2, 256, 0, sB>>>(H0, H1, b2, X0, X1, 64, 1);
    k_tgemm<32, 64, 1, 1><<<gGemm2, 256, 0, sB>>>(X0, X1, W3, H0, H1, 1);
    k_gather<0><<<gGath3, 256, 0, sB>>>(H0, H1, b3, af0, af1, 32, 1);
    k_fragB<<<(NT_TILES * 2 * 32 + 255) / 256, 256, 0, sB>>>();
    cudaEventRecord(evFragB, sB);

    // tail on sB
    cudaStreamWaitEvent(sB, evG0af, 0);
    k_tail<<<TAILB, 256, 0, sB>>>(att_w, tn_w, tn_wb, tn_bias);
    cudaEventRecord(evTail, sB);

    // simpass on main
    cudaStreamWaitEvent(0, evFragB, 0);
    dim3 hgrid((NN + 127) / 128, (NN + 127) / 128);
    k_sim0<<<hgrid, 256>>>();
    k_sim1<<<hgrid, 256>>>();

    // join
    cudaStreamWaitEvent(0, evTail, 0);
    k_head<<<1, 32>>>(fc1_w, fc1_b, fc2_w, fc2_b, out);
}

// round 16
// speedup vs baseline: 1.5346x; 1.0094x over previous
#include <cuda_runtime.h>
#include <cuda_fp16.h>
#include <math.h>

#define NN 10000
#define EE 320000
#define QP (EE / 4)
#define MT_TILES 632
#define NT_TILES 1264
#define TAILB 80
typedef unsigned long long u64;

// ---------------- device scratch ----------------
__device__ __half g_Hh[2][NN * 128];
__device__ __half g_Xh[2][NN * 128];
__device__ float g_af[2][NN * 32];
__device__ uint4 g_fA[MT_TILES * 2 * 32];
__device__ uint2 g_fB[NT_TILES * 2 * 32];
__device__ float g_dinv[2][NN];
__device__ int   g_indeg[2][NN];
__device__ int   g_rowstart[2][NN + 1];
__device__ int   g_blocksum[2][16];
__device__ int   g_lpos[2][EE];
__device__ int2  g_adjc[2][EE];
__device__ unsigned g_keymin, g_keymax;
__device__ unsigned g_hist[16 * 32];
__device__ unsigned g_barctr[8];
__device__ float g_meanraw[2][32];
__device__ float g_gc[2][32];
__device__ float g_pool[2][32];
__device__ float g_A[2][32 * 16];
__device__ float g_c[2][16];
__device__ float g_sAcc[2][16];
__device__ float g_s0[16];

// ---------------- helpers ----------------
__device__ __forceinline__ unsigned fkey(float f) {
    unsigned u = __float_as_uint(f);
    return (u & 0x80000000u) ? ~u : (u | 0x80000000u);
}
__device__ __forceinline__ float fdec(unsigned k) {
    return (k & 0x80000000u) ? __uint_as_float(k ^ 0x80000000u)
                             : __uint_as_float(~k);
}
__device__ __forceinline__ u64 dup2(float a) {
    u64 r;
    asm("mov.b64 %0, {%1, %1};" : "=l"(r) : "r"(__float_as_uint(a)));
    return r;
}
__device__ __forceinline__ void ffma2(u64& acc, u64 a, u64 b) {
    asm("fma.rn.f32x2 %0, %1, %2, %0;" : "+l"(acc) : "l"(a), "l"(b));
}
__device__ __forceinline__ void unpk(u64 v, float& lo, float& hi) {
    unsigned l, h;
    asm("mov.b64 {%0, %1}, %2;" : "=r"(l), "=r"(h) : "l"(v));
    lo = __uint_as_float(l); hi = __uint_as_float(h);
}
__device__ __forceinline__ unsigned h2pack(float a, float b) {
    __half2 h = __floats2half2_rn(a, b);
    return *(unsigned*)&h;
}
__device__ __forceinline__ void mma_f16(float c[4], uint4 a, uint2 b) {
    asm("mma.sync.aligned.m16n8k16.row.col.f32.f16.f16.f32 "
        "{%0,%1,%2,%3}, {%4,%5,%6,%7}, {%8,%9}, {%0,%1,%2,%3};"
        : "+f"(c[0]), "+f"(c[1]), "+f"(c[2]), "+f"(c[3])
        : "r"(a.x), "r"(a.y), "r"(a.z), "r"(a.w), "r"(b.x), "r"(b.y));
}
__device__ __forceinline__ void gridbar(int ph) {
    __syncthreads();
    if (threadIdx.x == 0) {
        __threadfence();
        unsigned t = atomicAdd(&g_barctr[ph], 1u) + 1;
        if (t < TAILB) {
            while (((volatile unsigned*)g_barctr)[ph] < TAILB) { }
        }
        __threadfence();
    }
    __syncthreads();
}

// ---------------- reset ----------------
__global__ void k_reset() {
    int t = threadIdx.x;
    for (int i = t; i < 2 * NN; i += 1024)
        ((int*)g_indeg)[i] = 0;
    if (t < 16 * 32) g_hist[t] = 0u;
    if (t < 32) {
        g_meanraw[0][t] = 0.f; g_meanraw[1][t] = 0.f;
        g_pool[0][t] = 0.f;    g_pool[1][t] = 0.f;
    }
    if (t < 16) { g_sAcc[0][t] = 0.f; g_sAcc[1][t] = 0.f; }
    if (t < 8) g_barctr[t] = 0u;
    if (t == 0) { g_keymin = 0xFFFFFFFFu; g_keymax = 0u; }
}

// ---------------- CSR build (4 edges / thread) ----------------
__global__ void k_indeg(const int* __restrict__ ei1, const int* __restrict__ ei2) {
    int t = blockIdx.x * 256 + threadIdx.x;
    if (t >= 2 * QP) return;
    int g = t >= QP;
    const int* ei = g ? ei2 : ei1;
    int e4 = (t - g * QP) * 4;
    int4 d = *(const int4*)&ei[EE + e4];
    int4 lp;
    lp.x = atomicAdd(&g_indeg[g][d.x], 1);
    lp.y = atomicAdd(&g_indeg[g][d.y], 1);
    lp.z = atomicAdd(&g_indeg[g][d.z], 1);
    lp.w = atomicAdd(&g_indeg[g][d.w], 1);
    *(int4*)&g_lpos[g][e4] = lp;
}

__global__ void k_scanA() {        // grid (10, 2), block 1024
    int cx = blockIdx.x, g = blockIdx.y, t = threadIdx.x;
    int lane = t & 31, w = t >> 5;
    __shared__ int warpsum[32];
    int i = cx * 1024 + t;
    int v = (i < NN) ? g_indeg[g][i] : 0;
    int x = v;
#pragma unroll
    for (int o = 1; o < 32; o <<= 1) {
        int y = __shfl_up_sync(0xffffffffu, x, o);
        if (lane >= o) x += y;
    }
    if (lane == 31) warpsum[w] = x;
    __syncthreads();
    if (w == 0) {
        int ws = warpsum[lane];
#pragma unroll
        for (int o = 1; o < 32; o <<= 1) {
            int y = __shfl_up_sync(0xffffffffu, ws, o);
            if (lane >= o) ws += y;
        }
        warpsum[lane] = ws;
    }
    __syncthreads();
    int excl = (x - v) + (w ? warpsum[w - 1] : 0);
    if (i < NN) {
        g_rowstart[g][i] = excl;
        g_dinv[g][i] = rsqrtf((float)v + 1.0f);
    }
    if (t == 1023) g_blocksum[g][cx] = excl + v;
}

__global__ void k_scanBC() {       // grid 2, block 1024
    int g = blockIdx.x, t = threadIdx.x;
    __shared__ int choff[11];
    if (t == 0) {
        int run = 0;
        for (int c = 0; c < 10; c++) { choff[c] = run; run += g_blocksum[g][c]; }
        choff[10] = run;
        g_rowstart[g][NN] = run;
    }
    __syncthreads();
#pragma unroll
    for (int c = 0; c < 10; c++) {
        int i = c * 1024 + t;
        if (i < NN) g_rowstart[g][i] += choff[c];
    }
}

__global__ void k_fill(const int* __restrict__ ei1, const int* __restrict__ ei2) {
    int t = blockIdx.x * 256 + threadIdx.x;
    if (t >= 2 * QP) return;
    int g = t >= QP;
    const int* ei = g ? ei2 : ei1;
    int e4 = (t - g * QP) * 4;
    int4 s = *(const int4*)&ei[e4];
    int4 d = *(const int4*)&ei[EE + e4];
    int4 lp = *(const int4*)&g_lpos[g][e4];
    float c0 = g_dinv[g][s.x] * g_dinv[g][d.x];
    float c1 = g_dinv[g][s.y] * g_dinv[g][d.y];
    float c2 = g_dinv[g][s.z] * g_dinv[g][d.z];
    float c3 = g_dinv[g][s.w] * g_dinv[g][d.w];
    g_adjc[g][g_rowstart[g][d.x] + lp.x] = make_int2(s.x, __float_as_int(c0));
    g_adjc[g][g_rowstart[g][d.y] + lp.y] = make_int2(s.y, __float_as_int(c1));
    g_adjc[g][g_rowstart[g][d.z] + lp.z] = make_int2(s.z, __float_as_int(c2));
    g_adjc[g][g_rowstart[g][d.w] + lp.w] = make_int2(s.w, __float_as_int(c3));
}

// ---------------- tiled GEMM (zoff selects graph) ----------------
template <int FOUT, int KTOT, int RELU, int INHALF>
__global__ void __launch_bounds__(256, 4)
k_tgemm(const void* __restrict__ X0v, const void* __restrict__ X1v,
        const float* __restrict__ W,
        __half* __restrict__ H0, __half* __restrict__ H1, int zoff) {
    constexpr int COLS = (FOUT >= 64) ? 64 : FOUT;
    constexpr int CPT = COLS / 32;
    __shared__ __align__(16) float As[32][68];
    __shared__ __align__(16) float Ws[32][COLS];
    int z = blockIdx.z + zoff;
    const void* Xv = z ? X1v : X0v;
    __half* H = z ? H1 : H0;
    int tid = threadIdx.x;
    int i0 = blockIdx.x * 64;
    int cb = blockIdx.y * COLS;
    int tx = tid & 31, ty = tid >> 5;
    u64 acc2[4][CPT];
#pragma unroll
    for (int r = 0; r < 4; r++)
#pragma unroll
        for (int c = 0; c < CPT; c++) acc2[r][c] = 0ull;

    for (int k0 = 0; k0 < KTOT; k0 += 32) {
        for (int idx = tid; idx < 512; idx += 256) {
            int r = idx >> 3, k4 = idx & 7;
            int row = i0 + r;
            float4 v = make_float4(0.f, 0.f, 0.f, 0.f);
            if (row < NN) {
                if (INHALF) {
                    uint2 raw = *(const uint2*)((const __half*)Xv + (size_t)row * KTOT + k0 + k4 * 4);
                    float2 a = __half22float2(*(__half2*)&raw.x);
                    float2 b = __half22float2(*(__half2*)&raw.y);
                    v = make_float4(a.x, a.y, b.x, b.y);
                } else {
                    v = *(const float4*)((const float*)Xv + (size_t)row * KTOT + k0 + k4 * 4);
                }
            }
            if (RELU) {
                v.x = fmaxf(v.x, 0.f); v.y = fmaxf(v.y, 0.f);
                v.z = fmaxf(v.z, 0.f); v.w = fmaxf(v.w, 0.f);
            }
            As[k4 * 4 + 0][r] = v.x; As[k4 * 4 + 1][r] = v.y;
            As[k4 * 4 + 2][r] = v.z; As[k4 * 4 + 3][r] = v.w;
        }
        for (int idx = tid; idx < 8 * COLS; idx += 256) {
            int j4 = idx % (COLS / 4), kk = idx / (COLS / 4);
            float4 w = *(const float4*)&W[(size_t)(k0 + kk) * FOUT + cb + j4 * 4];
            Ws[kk][j4 * 4 + 0] = w.x; Ws[kk][j4 * 4 + 1] = w.y;
            Ws[kk][j4 * 4 + 2] = w.z; Ws[kk][j4 * 4 + 3] = w.w;
        }
        __syncthreads();
#pragma unroll 4
        for (int k = 0; k < 32; k++) {
            u64 aa[4];
            {
                const ulonglong2* ap = (const ulonglong2*)&As[k][ty * 8];
                ulonglong2 t0 = ap[0], t1 = ap[1];
                aa[0] = t0.x; aa[1] = t0.y; aa[2] = t1.x; aa[3] = t1.y;
            }
            u64 bd[CPT];
            if (CPT == 2) {
                float2 b = *(const float2*)&Ws[k][tx * 2];
                bd[0] = dup2(b.x); bd[1] = dup2(b.y);
            } else {
                bd[0] = dup2(Ws[k][tx]);
            }
#pragma unroll
            for (int r = 0; r < 4; r++)
#pragma unroll
                for (int c = 0; c < CPT; c++) ffma2(acc2[r][c], aa[r], bd[c]);
        }
        __syncthreads();
    }
#pragma unroll
    for (int rp = 0; rp < 4; rp++) {
        int r0 = i0 + ty * 8 + 2 * rp;
        float lo[CPT], hi[CPT];
#pragma unroll
        for (int c = 0; c < CPT; c++) unpk(acc2[rp][c], lo[c], hi[c]);
        if (r0 < NN) {
            if (CPT == 2)
                *(__half2*)&H[(size_t)r0 * FOUT + cb + tx * 2] = __floats2half2_rn(lo[0], lo[1]);
            else
                H[(size_t)r0 * FOUT + cb + tx] = __float2half_rn(lo[0]);
        }
        if (r0 + 1 < NN) {
            if (CPT == 2)
                *(__half2*)&H[(size_t)(r0 + 1) * FOUT + cb + tx * 2] = __floats2half2_rn(hi[0], hi[1]);
            else
                H[(size_t)(r0 + 1) * FOUT + cb + tx] = __float2half_rn(hi[0]);
        }
    }
}

// ---------------- gather (zoff selects graph) ----------------
template <int OUTHALF>
__global__ void k_gather(const __half* __restrict__ H0, const __half* __restrict__ H1,
                         const float* __restrict__ b,
                         void* __restrict__ O0v, void* __restrict__ O1v, int Fout,
                         int zoff) {
    int z = blockIdx.z + zoff;
    const __half* H = z ? H1 : H0;
    int gpf = Fout >> 2;
    int idx = blockIdx.x * 256 + threadIdx.x;
    int node = idx / gpf;
    int c = idx - node * gpf;
    if (node >= NN) return;
    int rs = g_rowstart[z][node], re = g_rowstart[z][node + 1];
    float invdeg = 1.0f / ((float)(re - rs) + 1.0f);
    __half2 h01, h23;
    {
        uint2 raw = *(const uint2*)((const __half*)(H + (size_t)node * Fout) + c * 4);
        h01 = *(__half2*)&raw.x; h23 = *(__half2*)&raw.y;
    }
    float2 f01 = __half22float2(h01), f23 = __half22float2(h23);
    float4 bb = ((const float4*)b)[c];
    float4 acc;
    acc.x = f01.x * invdeg + bb.x; acc.y = f01.y * invdeg + bb.y;
    acc.z = f23.x * invdeg + bb.z; acc.w = f23.y * invdeg + bb.w;
    const int2* __restrict__ adjc = g_adjc[z];
#pragma unroll 4
    for (int e = rs; e < re; e++) {
        int2 sc = __ldg(&adjc[e]);
        float coef = __int_as_float(sc.y);
        uint2 raw = __ldg((const uint2*)(H + (size_t)sc.x * Fout) + c);
        float2 v01 = __half22float2(*(__half2*)&raw.x);
        float2 v23 = __half22float2(*(__half2*)&raw.y);
        acc.x += coef * v01.x; acc.y += coef * v01.y;
        acc.z += coef * v23.x; acc.w += coef * v23.y;
    }
    if (OUTHALF) {
        __half* O = (__half*)(z ? O1v : O0v);
        __half2 h0 = __floats2half2_rn(acc.x, acc.y);
        __half2 h1 = __floats2half2_rn(acc.z, acc.w);
        uint2 o;
        o.x = *(unsigned*)&h0; o.y = *(unsigned*)&h1;
        *(uint2*)(O + (size_t)node * Fout + c * 4) = o;
    } else {
        float* O = (float*)(z ? O1v : O0v);
        ((float4*)(O + (size_t)node * Fout))[c] = acc;
    }
}

// ---------------- fp16 fragment builders ----------------
__device__ __forceinline__ float afld(const float* af, int n, int k) {
    return (n < NN) ? af[n * 32 + k] : 0.f;
}
__global__ void k_fragA() {
    int wg = (blockIdx.x * 256 + threadIdx.x) >> 5;
    int lane = threadIdx.x & 31;
    if (wg >= MT_TILES * 2) return;
    int mt = wg >> 1, ks = wg & 1;
    const float* af = g_af[0];
    int r = mt * 16 + (lane >> 2);
    int kb = ks * 16 + (lane & 3) * 2;
    uint4 v;
    v.x = h2pack(afld(af, r,     kb),     afld(af, r,     kb + 1));
    v.y = h2pack(afld(af, r + 8, kb),     afld(af, r + 8, kb + 1));
    v.z = h2pack(afld(af, r,     kb + 8), afld(af, r,     kb + 9));
    v.w = h2pack(afld(af, r + 8, kb + 8), afld(af, r + 8, kb + 9));
    g_fA[(mt * 2 + ks) * 32 + lane] = v;
}
__global__ void k_fragB() {
    int wg = (blockIdx.x * 256 + threadIdx.x) >> 5;
    int lane = threadIdx.x & 31;
    if (wg >= NT_TILES * 2) return;
    int nt = wg >> 1, ks = wg & 1;
    const float* af = g_af[1];
    int n = nt * 8 + (lane >> 2);
    int kb = ks * 16 + (lane & 3) * 2;
    uint2 v;
    v.x = h2pack(afld(af, n, kb),     afld(af, n, kb + 1));
    v.y = h2pack(afld(af, n, kb + 8), afld(af, n, kb + 9));
    g_fB[(nt * 2 + ks) * 32 + lane] = v;
}

// ---------------- pass 0: exact min/max (quartered register tile) ----------------
__global__ void __launch_bounds__(256, 4)
k_sim0() {
    __shared__ __align__(16) uint2 shB[1024];
    int tid = threadIdx.x, lane = tid & 31, w = tid >> 5;
    int mt = blockIdx.y * 8 + w;
    int bx = blockIdx.x;
    {
        const uint4* src = (const uint4*)(g_fB + bx * 1024);
        uint4* dst = (uint4*)shB;
#pragma unroll
        for (int i = 0; i < 2; i++) dst[tid + 256 * i] = src[tid + 256 * i];
    }
    __syncthreads();
    uint4 afr[2];
#pragma unroll
    for (int ks = 0; ks < 2; ks++) afr[ks] = g_fA[(mt * 2 + ks) * 32 + lane];
    int r_lo = mt * 16 + (lane >> 2);
    int r_hi = r_lo + 8;
    int cbb = bx * 128 + 2 * (lane & 3);
    bool full = (mt < 625) && (bx < 78);
    bool vlo = r_lo < NN, vhi = r_hi < NN;
    float lmin = 3.4e38f, lmax = -3.4e38f;
#pragma unroll
    for (int jq = 0; jq < 4; jq++) {
        float c[4][4];
#pragma unroll
        for (int jj = 0; jj < 4; jj++)
#pragma unroll
            for (int r = 0; r < 4; r++) c[jj][r] = 0.f;
#pragma unroll
        for (int ks = 0; ks < 2; ks++)
#pragma unroll
            for (int jj = 0; jj < 4; jj++)
                mma_f16(c[jj], afr[ks], shB[((jq * 4 + jj) * 2 + ks) * 32 + lane]);
        if (full) {
#pragma unroll
            for (int jj = 0; jj < 4; jj++)
#pragma unroll
                for (int r = 0; r < 4; r++) {
                    lmin = fminf(lmin, c[jj][r]);
                    lmax = fmaxf(lmax, c[jj][r]);
                }
        } else {
#pragma unroll
            for (int jj = 0; jj < 4; jj++) {
                int c0 = cbb + (jq * 4 + jj) * 8;
                bool v0 = c0 < NN, v1 = c0 + 1 < NN;
                if (vlo && v0) { lmin = fminf(lmin, c[jj][0]); lmax = fmaxf(lmax, c[jj][0]); }
                if (vlo && v1) { lmin = fminf(lmin, c[jj][1]); lmax = fmaxf(lmax, c[jj][1]); }
                if (vhi && v0) { lmin = fminf(lmin, c[jj][2]); lmax = fmaxf(lmax, c[jj][2]); }
                if (vhi && v1) { lmin = fminf(lmin, c[jj][3]); lmax = fmaxf(lmax, c[jj][3]); }
            }
        }
    }
    for (int o = 16; o; o >>= 1) {
        lmin = fminf(lmin, __shfl_down_sync(0xffffffffu, lmin, o));
        lmax = fmaxf(lmax, __shfl_down_sync(0xffffffffu, lmax, o));
    }
    if (lane == 0) {
        atomicMin(&g_keymin, fkey(lmin));
        atomicMax(&g_keymax, fkey(lmax));
    }
}

// ---------------- pass 1: stratified 1/4-sampled histogram ----------------
__global__ void __launch_bounds__(256, 6)
k_sim1() {
    __shared__ __align__(16) uint2 shB[256];
    __shared__ unsigned sh[16];
    int tid = threadIdx.x, lane = tid & 31, w = tid >> 5;
    int mt = blockIdx.y * 8 + w;
    int bx = blockIdx.x;
    int joff = (blockIdx.y + bx) & 3;
    {
        int jj = tid >> 6, ks = (tid >> 5) & 1, ln = tid & 31;
        shB[tid] = g_fB[((bx * 16 + joff + 4 * jj) * 2 + ks) * 32 + ln];
    }
    if (tid < 16) sh[tid] = 0u;
    __syncthreads();
    uint4 afr[2];
#pragma unroll
    for (int ks = 0; ks < 2; ks++) afr[ks] = g_fA[(mt * 2 + ks) * 32 + lane];
    float c[4][4];
#pragma unroll
    for (int jj = 0; jj < 4; jj++)
#pragma unroll
        for (int r = 0; r < 4; r++) c[jj][r] = 0.f;
#pragma unroll
    for (int ks = 0; ks < 2; ks++)
#pragma unroll
        for (int jj = 0; jj < 4; jj++)
            mma_f16(c[jj], afr[ks], shB[(jj * 2 + ks) * 32 + lane]);

    float lo_r = fdec(g_keymin), hi_r = fdec(g_keymax);
    float s16 = 16.0f / ((hi_r - lo_r) + 1e-12f);
    float b16f = __fmaf_rn(-lo_r, s16, -0.5f);
    int r_lo = mt * 16 + (lane >> 2);
    int r_hi = r_lo + 8;
    int cbb = bx * 128 + 2 * (lane & 3);
    bool full = (mt < 625) && (bx < 78);
    u64 cl = 0ull, ch = 0ull;
    if (full) {
#pragma unroll
        for (int jj = 0; jj < 4; jj++)
#pragma unroll
            for (int r = 0; r < 4; r++) {
                float t = __fadd_rn(__fmaf_rn(c[jj][r], s16, b16f), 8388608.0f);
                unsigned u = __float_as_uint(t);
                u64 inc = 1ull << ((u & 7u) * 8u);
                if (u & 8u) ch += inc; else cl += inc;
            }
    } else {
        bool vr[2] = {r_lo < NN, r_hi < NN};
#pragma unroll
        for (int jj = 0; jj < 4; jj++) {
            int c0 = cbb + (joff + 4 * jj) * 8;
            bool vc[2] = {c0 < NN, c0 + 1 < NN};
#pragma unroll
            for (int r = 0; r < 4; r++) {
                if (!(vr[r >> 1] && vc[r & 1])) continue;
                float t = __fadd_rn(__fmaf_rn(c[jj][r], s16, b16f), 8388608.0f);
                unsigned u = __float_as_uint(t);
                u64 inc = 1ull << ((u & 7u) * 8u);
                if (u & 8u) ch += inc; else cl += inc;
            }
        }
    }
    const u64 M = 0x00FF00FF00FF00FFull;
    u64 e0 = cl & M, e1 = (cl >> 8) & M;
    u64 e2 = ch & M, e3 = (ch >> 8) & M;
#pragma unroll
    for (int o = 16; o; o >>= 1) {
        e0 += __shfl_down_sync(0xffffffffu, e0, o);
        e1 += __shfl_down_sync(0xffffffffu, e1, o);
        e2 += __shfl_down_sync(0xffffffffu, e2, o);
        e3 += __shfl_down_sync(0xffffffffu, e3, o);
    }
    if (lane == 0) {
#pragma unroll
        for (int i = 0; i < 4; i++) {
            unsigned v0 = (unsigned)((e0 >> (16 * i)) & 0xFFFFull);
            unsigned v1 = (unsigned)((e1 >> (16 * i)) & 0xFFFFull);
            unsigned v2 = (unsigned)((e2 >> (16 * i)) & 0xFFFFull);
            unsigned v3 = (unsigned)((e3 >> (16 * i)) & 0xFFFFull);
            if (v0) atomicAdd(&sh[2 * i], v0);
            if (v1) atomicAdd(&sh[2 * i + 1], v1);
            if (v2) atomicAdd(&sh[8 + 2 * i], v2);
            if (v3) atomicAdd(&sh[9 + 2 * i], v3);
        }
    }
    __syncthreads();
    if (tid < 16 && sh[tid]) atomicAdd(&g_hist[tid * 32], sh[tid]);
}

// ---------------- fused tail (attention + TN) ----------------
__global__ void __launch_bounds__(256, 4)
k_tail(const float* __restrict__ att_w,
       const float* __restrict__ tn_w, const float* __restrict__ tn_wb,
       const float* __restrict__ tn_bias) {
    int bid = blockIdx.x, tid = threadIdx.x;
    int z = bid >= (TAILB / 2);
    int lb = z ? bid - TAILB / 2 : bid;
    int lane = tid & 31;
    int wz = (lb * 256 + tid) >> 5;
    const int nwz = (TAILB / 2) * 256 / 32;
    const float* X = g_af[z];

    {
        float acc = 0.f;
        for (int n = wz; n < NN; n += nwz) acc += X[n * 32 + lane];
        atomicAdd(&g_meanraw[z][lane], acc);
    }
    gridbar(0);
    if (bid == 0 && tid < 64) {
        int g = tid >> 5, j = tid & 31;
        float acc = 0.f;
        const float invN = 1.0f / NN;
        for (int f = 0; f < 32; f++)
            acc += (g_meanraw[g][f] * invN) * att_w[f * 32 + j];
        g_gc[g][j] = tanhf(acc);
    }
    gridbar(1);
    {
        float gcv = g_gc[z][lane];
        float acc = 0.f;
        for (int n = wz; n < NN; n += nwz) {
            float x = X[n * 32 + lane];
            float p = x * gcv;
            for (int o = 16; o; o >>= 1) p += __shfl_xor_sync(0xffffffffu, p, o);
            float sig = 1.0f / (1.0f + expf(-p));
            acc += x * sig;
        }
        atomicAdd(&g_pool[z][lane], acc);
    }
    gridbar(2);
    if (bid == 0) {
        for (int t = tid; t < 1024; t += 256) {
            int slot = t >> 9, r = t & 511, f = r >> 4, k = r & 15;
            const float* e2 = g_pool[1 - slot];
            float acc = tn_wb[k * 64 + f];
            for (int gg = 0; gg < 32; gg++)
                acc += tn_w[f * 512 + gg * 16 + k] * e2[gg];
            g_A[slot][f * 16 + k] = acc;
        }
        if (tid < 32) {
            int sl = tid >> 4, kk = tid & 15;
            const float* e2b = g_pool[1 - sl];
            float cc = tn_bias[kk];
            for (int gg = 0; gg < 32; gg++)
                cc += tn_wb[kk * 64 + 32 + gg] * e2b[gg];
            g_c[sl][kk] = cc;
        }
        __syncthreads();
        if (tid < 16) {
            float a2 = g_c[0][tid];
            for (int f2 = 0; f2 < 32; f2++)
                a2 += g_pool[0][f2] * g_A[0][f2 * 16 + tid];
            g_s0[tid] = fmaxf(a2, 0.f);
        }
    }
    gridbar(3);
    {
        float acc = 0.f;
        for (int n = wz; n < NN; n += nwz) {
            float x = X[n * 32 + lane];
            float v = (lane < 16) ? g_c[z][lane] : 0.f;
#pragma unroll
            for (int f = 0; f < 32; f++) {
                float xf = __shfl_sync(0xffffffffu, x, f);
                if (lane < 16) v += xf * g_A[z][f * 16 + lane];
            }
            if (lane < 16) acc += fmaxf(v, 0.f);
        }
        if (lane < 16) atomicAdd(&g_sAcc[z][lane], acc);
    }
}

// ---------------- final head ----------------
__global__ void k_head(const float* __restrict__ fc1_w, const float* __restrict__ fc1_b,
                       const float* __restrict__ fc2_w, const float* __restrict__ fc2_b,
                       float* __restrict__ out) {
    if (threadIdx.x != 0) return;
    float sc[64];
    const float invN = 1.0f / NN;
    for (int k = 0; k < 16; k++) {
        sc[k]      = g_s0[k];
        sc[16 + k] = g_sAcc[0][k] * invN;
        sc[32 + k] = g_sAcc[1][k] * invN;
    }
    float hf[16], hsum = 0.f;
    for (int b = 0; b < 16; b++) {
        u64 c4 = 4ull * (u64)g_hist[b * 32];
        if (c4 > 16777216ull) c4 = 16777216ull;
        hf[b] = (float)c4;
        hsum += hf[b];
    }
    for (int b = 0; b < 16; b++) sc[48 + b] = hf[b] / hsum;
    float o2 = fc2_b[0];
    for (int j = 0; j < 16; j++) {
        float a = fc1_b[j];
        for (int i = 0; i < 64; i++) a += sc[i] * fc1_w[i * 16 + j];
        a = fmaxf(a, 0.f);
        o2 += a * fc2_w[j];
    }
    out[0] = 1.0f / (1.0f + expf(-o2));
}

// ---------------- host driver (dual-stream, R13 topology) ----------------
extern "C" void kernel_launch(void* const* d_in, const int* in_sizes, int n_in,
                              void* d_out, int out_size) {
    const float* feat1 = (const float*)d_in[0];
    const float* feat2 = (const float*)d_in[1];
    const int* ei1 = (const int*)d_in[2];
    const int* ei2 = (const int*)d_in[3];
    const float* W1 = (const float*)d_in[4];
    const float* b1 = (const float*)d_in[5];
    const float* W2 = (const float*)d_in[6];
    const float* b2 = (const float*)d_in[7];
    const float* W3 = (const float*)d_in[8];
    const float* b3 = (const float*)d_in[9];
    const float* att_w = (const float*)d_in[10];
    const float* tn_w = (const float*)d_in[11];
    const float* tn_wb = (const float*)d_in[12];
    const float* tn_bias = (const float*)d_in[13];
    const float* fc1_w = (const float*)d_in[14];
    const float* fc1_b = (const float*)d_in[15];
    const float* fc2_w = (const float*)d_in[16];
    const float* fc2_b = (const float*)d_in[17];
    float* out = (float*)d_out;

    __half *H0, *H1, *X0, *X1;
    float *af0, *af1;
    cudaGetSymbolAddress((void**)&H0, g_Hh);  H1 = H0 + NN * 128;
    cudaGetSymbolAddress((void**)&X0, g_Xh);  X1 = X0 + NN * 128;
    cudaGetSymbolAddress((void**)&af0, g_af); af1 = af0 + NN * 32;

    static cudaStream_t sB = nullptr;
    static cudaEvent_t evStart, evT1, evCSR, evG0af, evFragB, evTail;
    if (!sB) {
        cudaStreamCreateWithFlags(&sB, cudaStreamNonBlocking);
        cudaEventCreateWithFlags(&evStart, cudaEventDisableTiming);
        cudaEventCreateWithFlags(&evT1, cudaEventDisableTiming);
        cudaEventCreateWithFlags(&evCSR, cudaEventDisableTiming);
        cudaEventCreateWithFlags(&evG0af, cudaEventDisableTiming);
        cudaEventCreateWithFlags(&evFragB, cudaEventDisableTiming);
        cudaEventCreateWithFlags(&evTail, cudaEventDisableTiming);
    }

    dim3 gGemm1((NN + 63) / 64, 2, 2);
    dim3 gGemm2((NN + 63) / 64, 1, 1);
    dim3 gGath1((NN * 32 + 255) / 256, 1, 1);
    dim3 gGath2((NN * 16 + 255) / 256, 1, 1);
    dim3 gGath3((NN * 8 + 255) / 256, 1, 1);

    // fork 1: layer-1 GEMM (both graphs) on sB, CSR on main
    cudaEventRecord(evStart, 0);
    cudaStreamWaitEvent(sB, evStart, 0);
    k_tgemm<128, 128, 0, 0><<<gGemm1, 256, 0, sB>>>(feat1, feat2, W1, H0, H1, 0);
    cudaEventRecord(evT1, sB);

    k_reset<<<1, 1024>>>();
    k_indeg<<<(2 * QP + 255) / 256, 256>>>(ei1, ei2);
    {
        dim3 sg(10, 2);
        k_scanA<<<sg, 1024>>>();
    }
    k_scanBC<<<2, 1024>>>();
    k_fill<<<(2 * QP + 255) / 256, 256>>>(ei1, ei2);
    cudaEventRecord(evCSR, 0);

    // graph-0 chain on main
    cudaStreamWaitEvent(0, evT1, 0);
    k_gather<1><<<gGath1, 256>>>(H0, H1, b1, X0, X1, 128, 0);
    k_tgemm<64, 128, 1, 1><<<gGemm2, 256>>>(X0, X1, W2, H0, H1, 0);
    k_gather<1><<<gGath2, 256>>>(H0, H1, b2, X0, X1, 64, 0);
    k_tgemm<32, 64, 1, 1><<<gGemm2, 256>>>(X0, X1, W3, H0, H1, 0);
    k_gather<0><<<gGath3, 256>>>(H0, H1, b3, af0, af1, 32, 0);
    cudaEventRecord(evG0af, 0);
    k_fragA<<<(MT_TILES * 2 * 32 + 255) / 256, 256>>>();

    // graph-1 chain on sB
    cudaStreamWaitEvent(sB, evCSR, 0);
    k_gather<1><<<gGath1, 256, 0, sB>>>(H0, H1, b1, X0, X1, 128, 1);
    k_tgemm<64, 128, 1, 1><<<gGemm2, 256, 0, sB>>>(X0, X1, W2, H0, H1, 1);
    k_gather<1><<<gGath2, 256, 0, sB>>>(H0, H1, b2, X0, X1, 64, 1);
    k_tgemm<32, 64, 1, 1><<<gGemm2, 256, 0, sB>>>(X0, X1, W3, H0, H1, 1);
    k_gather<0><<<gGath3, 256, 0, sB>>>(H0, H1, b3, af0, af1, 32, 1);
    k_fragB<<<(NT_TILES * 2 * 32 + 255) / 256, 256, 0, sB>>>();
    cudaEventRecord(evFragB, sB);

    // tail on sB
    cudaStreamWaitEvent(sB, evG0af, 0);
    k_tail<<<TAILB, 256, 0, sB>>>(att_w, tn_w, tn_wb, tn_bias);
    cudaEventRecord(evTail, sB);

    // simpass on main
    cudaStreamWaitEvent(0, evFragB, 0);
    dim3 hgrid((NN + 127) / 128, (NN + 127) / 128);
    k_sim0<<<hgrid, 256>>>();
    k_sim1<<<hgrid, 256>>>();

    // join
    cudaStreamWaitEvent(0, evTail, 0);
    k_head<<<1, 32>>>(fc1_w, fc1_b, fc2_w, fc2_b, out);
}